// round 2
// baseline (speedup 1.0000x reference)
#include <cuda_runtime.h>
#include <cstdint>

#define NN 100000
#define NE 1200000
#define NF 128
#define NH 64
#define NG 256

// ---------------- device scratch (no allocations allowed) ----------------
__device__ int   g_cnt[NN];
__device__ float g_dinv[NN];
__device__ int   g_rowptr[NN + 1];
__device__ int   g_cursor[NN];
__device__ int   g_csr_src[NE];
__device__ float g_csr_norm[NE];
__device__ float g_h [NN * NH];   // gemm output buffer (reused by both convs)
__device__ float g_o1[NN * NH];   // conv1 output (post-relu)
__device__ float g_pooled[NG * NH];
__device__ int   g_gcnt[NG];

// ---------------- init ----------------
__global__ void init_k() {
    int i = blockIdx.x * blockDim.x + threadIdx.x;
    if (i < NN) g_cnt[i] = 0;
    if (i < NG * NH) g_pooled[i] = 0.f;
    if (i < NG) g_gcnt[i] = 0;
}

// ---------------- degree count over dst (self-loops handled analytically) ----------------
__global__ void count_k(const int* __restrict__ dst) {
    int e = blockIdx.x * blockDim.x + threadIdx.x;
    if (e < NE) atomicAdd(&g_cnt[dst[e]], 1);
}

__global__ void dinv_k() {
    int i = blockIdx.x * blockDim.x + threadIdx.x;
    if (i < NN) g_dinv[i] = rsqrtf((float)(g_cnt[i] + 1));  // +1 = self loop
}

// ---------------- single-block exclusive scan -> rowptr & cursor ----------------
__global__ void scan_k() {
    __shared__ int sm[1024];
    int t = threadIdx.x;
    const int C = (NN + 1023) / 1024;
    int beg = t * C;
    int end = beg + C; if (end > NN) end = NN;
    int s = 0;
    for (int i = beg; i < end; i++) s += g_cnt[i];
    sm[t] = s;
    __syncthreads();
    // Hillis-Steele inclusive scan
    for (int off = 1; off < 1024; off <<= 1) {
        int v = (t >= off) ? sm[t - off] : 0;
        __syncthreads();
        sm[t] += v;
        __syncthreads();
    }
    int run = sm[t] - s;  // exclusive prefix
    for (int i = beg; i < end; i++) {
        g_rowptr[i] = run;
        g_cursor[i] = run;
        run += g_cnt[i];
    }
    if (t == 1023) g_rowptr[NN] = sm[1023];
}

// ---------------- scatter edges into CSR (by dst), precompute norms ----------------
__global__ void scatter_k(const int* __restrict__ src,
                          const int* __restrict__ dst) {
    int e = blockIdx.x * blockDim.x + threadIdx.x;
    if (e < NE) {
        int s = src[e];
        int d = dst[e];
        int pos = atomicAdd(&g_cursor[d], 1);
        g_csr_src[pos] = s;
        g_csr_norm[pos] = g_dinv[s] * g_dinv[d];
    }
}

// ---------------- fp32 SGEMM: C[M x 64] = A[M x K] @ W[K x 64] ----------------
// 64x64 tile, BK=16, 256 threads, 4x4 microtile. C is always g_h.
// SRC_O1: A comes from g_o1 (conv2), else from the x pointer (conv1).
template <int K, bool SRC_O1>
__global__ void gemm64_k(const float* __restrict__ Ain,
                         const float* __restrict__ W, int M) {
    const float* __restrict__ A = SRC_O1 ? (const float*)g_o1 : Ain;
    float* __restrict__ C = g_h;
    __shared__ float As[16][68];  // transposed: As[k][m], padded
    __shared__ float Bs[16][64];  // Bs[k][n]

    int tid = threadIdx.x;
    int tx = tid & 15, ty = tid >> 4;
    int rowBase = blockIdx.x * 64;

    float4 acc0 = make_float4(0, 0, 0, 0);
    float4 acc1 = make_float4(0, 0, 0, 0);
    float4 acc2 = make_float4(0, 0, 0, 0);
    float4 acc3 = make_float4(0, 0, 0, 0);

    for (int k0 = 0; k0 < K; k0 += 16) {
        {   // load A tile (64 rows x 16 k), transpose into smem
            int r  = tid >> 2;          // 0..63
            int kq = (tid & 3) * 4;     // 0,4,8,12
            int row = rowBase + r;
            float4 a = make_float4(0, 0, 0, 0);
            if (row < M) a = *(const float4*)&A[(size_t)row * K + k0 + kq];
            As[kq + 0][r] = a.x;
            As[kq + 1][r] = a.y;
            As[kq + 2][r] = a.z;
            As[kq + 3][r] = a.w;
        }
        {   // load W tile (16 k x 64 n)
            int kr = tid >> 4;          // 0..15
            int nq = (tid & 15) * 4;    // 0..60
            *(float4*)&Bs[kr][nq] = *(const float4*)&W[(size_t)(k0 + kr) * 64 + nq];
        }
        __syncthreads();
#pragma unroll
        for (int k = 0; k < 16; k++) {
            float4 a = *(float4*)&As[k][ty * 4];
            float4 b = *(float4*)&Bs[k][tx * 4];
            acc0.x = fmaf(a.x, b.x, acc0.x); acc0.y = fmaf(a.x, b.y, acc0.y);
            acc0.z = fmaf(a.x, b.z, acc0.z); acc0.w = fmaf(a.x, b.w, acc0.w);
            acc1.x = fmaf(a.y, b.x, acc1.x); acc1.y = fmaf(a.y, b.y, acc1.y);
            acc1.z = fmaf(a.y, b.z, acc1.z); acc1.w = fmaf(a.y, b.w, acc1.w);
            acc2.x = fmaf(a.z, b.x, acc2.x); acc2.y = fmaf(a.z, b.y, acc2.y);
            acc2.z = fmaf(a.z, b.z, acc2.z); acc2.w = fmaf(a.z, b.w, acc2.w);
            acc3.x = fmaf(a.w, b.x, acc3.x); acc3.y = fmaf(a.w, b.y, acc3.y);
            acc3.z = fmaf(a.w, b.z, acc3.z); acc3.w = fmaf(a.w, b.w, acc3.w);
        }
        __syncthreads();
    }
    int r0 = rowBase + ty * 4;
    if (r0 + 0 < M) *(float4*)&C[(size_t)(r0 + 0) * 64 + tx * 4] = acc0;
    if (r0 + 1 < M) *(float4*)&C[(size_t)(r0 + 1) * 64 + tx * 4] = acc1;
    if (r0 + 2 < M) *(float4*)&C[(size_t)(r0 + 2) * 64 + tx * 4] = acc2;
    if (r0 + 3 < M) *(float4*)&C[(size_t)(r0 + 3) * 64 + tx * 4] = acc3;
}

// ---------------- CSR gather aggregation (warp per node), fused epilogue ----------------
// reads g_h, conv1: writes relu(agg + dinv^2*h + b) -> g_o1
// conv2: pools (agg + dinv^2*h + b) into g_pooled / g_gcnt
template <bool RELU, bool POOL>
__global__ void gather_k(const float* __restrict__ bias,
                         const int* __restrict__ batch) {
    int node = (blockIdx.x * blockDim.x + threadIdx.x) >> 5;
    if (node >= NN) return;
    int lane = threadIdx.x & 31;

    int beg = g_rowptr[node];
    int end = g_rowptr[node + 1];
    const float2* __restrict__ h2 = (const float2*)g_h;

    float2 acc = make_float2(0.f, 0.f);
    for (int j = beg; j < end; j++) {
        int s = __ldg(&g_csr_src[j]);
        float nrm = __ldg(&g_csr_norm[j]);
        float2 v = __ldg(&h2[(size_t)s * 32 + lane]);
        acc.x = fmaf(nrm, v.x, acc.x);
        acc.y = fmaf(nrm, v.y, acc.y);
    }
    float di = g_dinv[node];
    float sn = di * di;
    float2 hv = h2[(size_t)node * 32 + lane];
    acc.x = fmaf(sn, hv.x, acc.x) + bias[2 * lane];
    acc.y = fmaf(sn, hv.y, acc.y) + bias[2 * lane + 1];
    if (RELU) {
        acc.x = fmaxf(acc.x, 0.f);
        acc.y = fmaxf(acc.y, 0.f);
    }
    if (POOL) {
        int g = batch[node];
        atomicAdd(&g_pooled[g * 64 + 2 * lane], acc.x);
        atomicAdd(&g_pooled[g * 64 + 2 * lane + 1], acc.y);
        if (lane == 0) atomicAdd(&g_gcnt[g], 1);
    } else {
        ((float2*)g_o1)[(size_t)node * 32 + lane] = acc;
    }
}

// ---------------- final: out[g] = dot(pooled[g], Wl)/cnt + bl ----------------
__global__ void final_k(const float* __restrict__ Wl,
                        const float* __restrict__ bl,
                        float* __restrict__ out) {
    int g = (blockIdx.x * blockDim.x + threadIdx.x) >> 5;
    if (g >= NG) return;
    int lane = threadIdx.x & 31;
    float2 p = ((const float2*)g_pooled)[g * 32 + lane];
    float2 w = ((const float2*)Wl)[lane];
    float v = p.x * w.x + p.y * w.y;
#pragma unroll
    for (int o = 16; o; o >>= 1) v += __shfl_xor_sync(0xffffffffu, v, o);
    if (lane == 0) {
        float c = (float)g_gcnt[g];
        out[g] = v / fmaxf(c, 1.f) + bl[0];
    }
}

// ---------------- launch ----------------
extern "C" void kernel_launch(void* const* d_in, const int* in_sizes, int n_in,
                              void* d_out, int out_size) {
    const float* x     = (const float*)d_in[0];
    const int*   ei    = (const int*)d_in[1];    // int32! (JAX x64 disabled)
    const int*   batch = (const int*)d_in[2];    // int32!
    const float* W1    = (const float*)d_in[3];
    const float* b1    = (const float*)d_in[4];
    const float* W2    = (const float*)d_in[5];
    const float* b2    = (const float*)d_in[6];
    const float* Wl    = (const float*)d_in[7];
    const float* bl    = (const float*)d_in[8];
    float* out = (float*)d_out;

    const int* src = ei;
    const int* dst = ei + NE;

    init_k   <<<(NN + 255) / 256, 256>>>();
    count_k  <<<(NE + 255) / 256, 256>>>(dst);
    dinv_k   <<<(NN + 255) / 256, 256>>>();
    scan_k   <<<1, 1024>>>();
    scatter_k<<<(NE + 255) / 256, 256>>>(src, dst);

    int gemmGrid   = (NN + 63) / 64;
    int gatherGrid = (NN * 32 + 255) / 256;  // warp per node, 8 warps/block

    // conv1: h = x @ W1 ; o1 = relu(agg(h) + b1)
    gemm64_k<NF, false><<<gemmGrid, 256>>>(x, W1, NN);
    gather_k<true, false><<<gatherGrid, 256>>>(b1, batch);

    // conv2: h = o1 @ W2 ; pool(agg(h) + b2)
    gemm64_k<NH, true><<<gemmGrid, 256>>>(nullptr, W2, NN);
    gather_k<false, true><<<gatherGrid, 256>>>(b2, batch);

    final_k<<<(NG * 32 + 255) / 256, 256>>>(Wl, bl, out);
}

// round 3
// speedup vs baseline: 1.6728x; 1.6728x over previous
#include <cuda_runtime.h>
#include <cstdint>

#define NN 100000
#define NE 1200000
#define NF 128
#define NH 64
#define NG 256

#define TILE 512
#define NT ((NN + TILE - 1) / TILE)   // 196 tiles

// ---------------- device scratch (no allocations allowed) ----------------
__device__ int   g_cnt[NN];
__device__ float g_dinv[NN];
__device__ int   g_rowptr[NN + 1];
__device__ int   g_cursor[NN];
__device__ int   g_csr_src[NE];
__device__ float g_csr_norm[NE];
__device__ int   g_tsum[NT];
__device__ int   g_toff[NT];
__device__ float g_h [NN * NH];   // gemm output buffer (reused by both convs)
__device__ float g_o1[NN * NH];   // conv1 output (post-relu)
__device__ float g_pooled[NG * NH];
__device__ int   g_gcnt[NG];

// ---------------- init ----------------
__global__ void init_k() {
    int i = blockIdx.x * blockDim.x + threadIdx.x;
    if (i < NN) g_cnt[i] = 0;
    if (i < NG * NH) g_pooled[i] = 0.f;
    if (i < NG) g_gcnt[i] = 0;
}

// ---------------- degree count over dst (self-loops handled analytically) ----------------
__global__ void count_k(const int* __restrict__ dst) {
    int e = blockIdx.x * blockDim.x + threadIdx.x;
    if (e < NE) atomicAdd(&g_cnt[dst[e]], 1);
}

__global__ void dinv_k() {
    int i = blockIdx.x * blockDim.x + threadIdx.x;
    if (i < NN) g_dinv[i] = rsqrtf((float)(g_cnt[i] + 1));  // +1 = self loop
}

// ---------------- stage 1: per-tile sums (full-chip parallel) ----------------
__global__ void tsum_k() {
    __shared__ int sm[TILE];
    int t = threadIdx.x;
    int i = blockIdx.x * TILE + t;
    sm[t] = (i < NN) ? g_cnt[i] : 0;
    __syncthreads();
#pragma unroll
    for (int off = TILE / 2; off > 0; off >>= 1) {
        if (t < off) sm[t] += sm[t + off];
        __syncthreads();
    }
    if (t == 0) g_tsum[blockIdx.x] = sm[0];
}

// ---------------- stage 2: scan 196 tile sums (tiny) ----------------
__global__ void toff_k() {
    __shared__ int sm[256];
    int t = threadIdx.x;
    int v = (t < NT) ? g_tsum[t] : 0;
    sm[t] = v;
    __syncthreads();
#pragma unroll
    for (int off = 1; off < 256; off <<= 1) {
        int u = (t >= off) ? sm[t - off] : 0;
        __syncthreads();
        sm[t] += u;
        __syncthreads();
    }
    if (t < NT) g_toff[t] = sm[t] - v;     // exclusive
    if (t == 255) g_rowptr[NN] = sm[255];  // total (== NE)
}

// ---------------- stage 3: per-tile exclusive scan -> rowptr & cursor ----------------
__global__ void tscan_k() {
    __shared__ int sm[TILE];
    int t = threadIdx.x;
    int i = blockIdx.x * TILE + t;
    int v = (i < NN) ? g_cnt[i] : 0;
    sm[t] = v;
    __syncthreads();
#pragma unroll
    for (int off = 1; off < TILE; off <<= 1) {
        int u = (t >= off) ? sm[t - off] : 0;
        __syncthreads();
        sm[t] += u;
        __syncthreads();
    }
    if (i < NN) {
        int pos = g_toff[blockIdx.x] + sm[t] - v;  // exclusive prefix
        g_rowptr[i] = pos;
        g_cursor[i] = pos;
    }
}

// ---------------- scatter edges into CSR (by dst), precompute norms ----------------
__global__ void scatter_k(const int* __restrict__ src,
                          const int* __restrict__ dst) {
    int e = blockIdx.x * blockDim.x + threadIdx.x;
    if (e < NE) {
        int s = src[e];
        int d = dst[e];
        int pos = atomicAdd(&g_cursor[d], 1);
        g_csr_src[pos] = s;
        g_csr_norm[pos] = g_dinv[s] * g_dinv[d];
    }
}

// ---------------- fp32 SGEMM: C[M x 64] = A[M x K] @ W[K x 64] ----------------
// 64x64 tile, BK=16, 256 threads, 4x4 microtile. C is always g_h.
template <int K, bool SRC_O1>
__global__ void gemm64_k(const float* __restrict__ Ain,
                         const float* __restrict__ W, int M) {
    const float* __restrict__ A = SRC_O1 ? (const float*)g_o1 : Ain;
    float* __restrict__ C = g_h;
    __shared__ float As[16][68];  // transposed: As[k][m], padded
    __shared__ float Bs[16][64];  // Bs[k][n]

    int tid = threadIdx.x;
    int tx = tid & 15, ty = tid >> 4;
    int rowBase = blockIdx.x * 64;

    float4 acc0 = make_float4(0, 0, 0, 0);
    float4 acc1 = make_float4(0, 0, 0, 0);
    float4 acc2 = make_float4(0, 0, 0, 0);
    float4 acc3 = make_float4(0, 0, 0, 0);

    for (int k0 = 0; k0 < K; k0 += 16) {
        {   // load A tile (64 rows x 16 k), transpose into smem
            int r  = tid >> 2;          // 0..63
            int kq = (tid & 3) * 4;     // 0,4,8,12
            int row = rowBase + r;
            float4 a = make_float4(0, 0, 0, 0);
            if (row < M) a = *(const float4*)&A[(size_t)row * K + k0 + kq];
            As[kq + 0][r] = a.x;
            As[kq + 1][r] = a.y;
            As[kq + 2][r] = a.z;
            As[kq + 3][r] = a.w;
        }
        {   // load W tile (16 k x 64 n)
            int kr = tid >> 4;          // 0..15
            int nq = (tid & 15) * 4;    // 0..60
            *(float4*)&Bs[kr][nq] = *(const float4*)&W[(size_t)(k0 + kr) * 64 + nq];
        }
        __syncthreads();
#pragma unroll
        for (int k = 0; k < 16; k++) {
            float4 a = *(float4*)&As[k][ty * 4];
            float4 b = *(float4*)&Bs[k][tx * 4];
            acc0.x = fmaf(a.x, b.x, acc0.x); acc0.y = fmaf(a.x, b.y, acc0.y);
            acc0.z = fmaf(a.x, b.z, acc0.z); acc0.w = fmaf(a.x, b.w, acc0.w);
            acc1.x = fmaf(a.y, b.x, acc1.x); acc1.y = fmaf(a.y, b.y, acc1.y);
            acc1.z = fmaf(a.y, b.z, acc1.z); acc1.w = fmaf(a.y, b.w, acc1.w);
            acc2.x = fmaf(a.z, b.x, acc2.x); acc2.y = fmaf(a.z, b.y, acc2.y);
            acc2.z = fmaf(a.z, b.z, acc2.z); acc2.w = fmaf(a.z, b.w, acc2.w);
            acc3.x = fmaf(a.w, b.x, acc3.x); acc3.y = fmaf(a.w, b.y, acc3.y);
            acc3.z = fmaf(a.w, b.z, acc3.z); acc3.w = fmaf(a.w, b.w, acc3.w);
        }
        __syncthreads();
    }
    int r0 = rowBase + ty * 4;
    if (r0 + 0 < M) *(float4*)&C[(size_t)(r0 + 0) * 64 + tx * 4] = acc0;
    if (r0 + 1 < M) *(float4*)&C[(size_t)(r0 + 1) * 64 + tx * 4] = acc1;
    if (r0 + 2 < M) *(float4*)&C[(size_t)(r0 + 2) * 64 + tx * 4] = acc2;
    if (r0 + 3 < M) *(float4*)&C[(size_t)(r0 + 3) * 64 + tx * 4] = acc3;
}

// ---------------- CSR gather aggregation (warp per node), fused epilogue ----------------
template <bool RELU, bool POOL>
__global__ void gather_k(const float* __restrict__ bias,
                         const int* __restrict__ batch) {
    int node = (blockIdx.x * blockDim.x + threadIdx.x) >> 5;
    if (node >= NN) return;
    int lane = threadIdx.x & 31;

    int beg = g_rowptr[node];
    int end = g_rowptr[node + 1];
    const float2* __restrict__ h2 = (const float2*)g_h;

    float2 acc = make_float2(0.f, 0.f);
    for (int j = beg; j < end; j++) {
        int s = __ldg(&g_csr_src[j]);
        float nrm = __ldg(&g_csr_norm[j]);
        float2 v = __ldg(&h2[(size_t)s * 32 + lane]);
        acc.x = fmaf(nrm, v.x, acc.x);
        acc.y = fmaf(nrm, v.y, acc.y);
    }
    float di = g_dinv[node];
    float sn = di * di;
    float2 hv = h2[(size_t)node * 32 + lane];
    acc.x = fmaf(sn, hv.x, acc.x) + bias[2 * lane];
    acc.y = fmaf(sn, hv.y, acc.y) + bias[2 * lane + 1];
    if (RELU) {
        acc.x = fmaxf(acc.x, 0.f);
        acc.y = fmaxf(acc.y, 0.f);
    }
    if (POOL) {
        int g = batch[node];
        atomicAdd(&g_pooled[g * 64 + 2 * lane], acc.x);
        atomicAdd(&g_pooled[g * 64 + 2 * lane + 1], acc.y);
        if (lane == 0) atomicAdd(&g_gcnt[g], 1);
    } else {
        ((float2*)g_o1)[(size_t)node * 32 + lane] = acc;
    }
}

// ---------------- final: out[g] = dot(pooled[g], Wl)/cnt + bl ----------------
__global__ void final_k(const float* __restrict__ Wl,
                        const float* __restrict__ bl,
                        float* __restrict__ out) {
    int g = (blockIdx.x * blockDim.x + threadIdx.x) >> 5;
    if (g >= NG) return;
    int lane = threadIdx.x & 31;
    float2 p = ((const float2*)g_pooled)[g * 32 + lane];
    float2 w = ((const float2*)Wl)[lane];
    float v = p.x * w.x + p.y * w.y;
#pragma unroll
    for (int o = 16; o; o >>= 1) v += __shfl_xor_sync(0xffffffffu, v, o);
    if (lane == 0) {
        float c = (float)g_gcnt[g];
        out[g] = v / fmaxf(c, 1.f) + bl[0];
    }
}

// ---------------- launch ----------------
extern "C" void kernel_launch(void* const* d_in, const int* in_sizes, int n_in,
                              void* d_out, int out_size) {
    const float* x     = (const float*)d_in[0];
    const int*   ei    = (const int*)d_in[1];    // int32 (JAX x64 disabled)
    const int*   batch = (const int*)d_in[2];    // int32
    const float* W1    = (const float*)d_in[3];
    const float* b1    = (const float*)d_in[4];
    const float* W2    = (const float*)d_in[5];
    const float* b2    = (const float*)d_in[6];
    const float* Wl    = (const float*)d_in[7];
    const float* bl    = (const float*)d_in[8];
    float* out = (float*)d_out;

    const int* src = ei;
    const int* dst = ei + NE;

    init_k   <<<(NN + 255) / 256, 256>>>();
    count_k  <<<(NE + 255) / 256, 256>>>(dst);
    dinv_k   <<<(NN + 255) / 256, 256>>>();
    tsum_k   <<<NT, TILE>>>();
    toff_k   <<<1, 256>>>();
    tscan_k  <<<NT, TILE>>>();
    scatter_k<<<(NE + 255) / 256, 256>>>(src, dst);

    int gemmGrid   = (NN + 63) / 64;
    int gatherGrid = (NN * 32 + 255) / 256;  // warp per node, 8 warps/block

    // conv1: h = x @ W1 ; o1 = relu(agg(h) + b1)
    gemm64_k<NF, false><<<gemmGrid, 256>>>(x, W1, NN);
    gather_k<true, false><<<gatherGrid, 256>>>(b1, batch);

    // conv2: h = o1 @ W2 ; pool(agg(h) + b2)
    gemm64_k<NH, true><<<gemmGrid, 256>>>(nullptr, W2, NN);
    gather_k<false, true><<<gatherGrid, 256>>>(b2, batch);

    final_k<<<(NG * 32 + 255) / 256, 256>>>(Wl, bl, out);
}

// round 4
// speedup vs baseline: 2.1089x; 1.2607x over previous
#include <cuda_runtime.h>
#include <cstdint>

#define NN 100000
#define NE 1200000
#define NF 128
#define NH 64
#define NG 256

#define TILE 512
#define NT ((NN + TILE - 1) / TILE)   // 196 tiles

// ---------------- device scratch (no allocations allowed) ----------------
__device__ int   g_cnt[NN];
__device__ float g_dinv[NN];
__device__ int   g_rowptr[NN + 1];
__device__ int   g_cursor[NN];
__device__ int2  g_csr[NE];           // {src, norm bits}
__device__ int   g_tsum[NT];
__device__ int   g_toff[NT];
__device__ float g_h[NN * NH];        // gemm1 output (x @ W1)
__device__ float g_z[NN];             // per-node scalar z = relu-row . (W2@Wl)
__device__ float g_w64[NH];           // W2 @ Wl
__device__ float g_b2wl;              // b2 . Wl
__device__ float g_pool_s[NG];
__device__ int   g_gcnt[NG];

// ---------------- init ----------------
__global__ void init_k() {
    int i = blockIdx.x * blockDim.x + threadIdx.x;
    if (i < NN) g_cnt[i] = 0;
    if (i < NG) { g_pool_s[i] = 0.f; g_gcnt[i] = 0; }
}

// ---------------- degree count over dst ----------------
__global__ void count_k(const int* __restrict__ dst) {
    int e = blockIdx.x * blockDim.x + threadIdx.x;
    if (e < NE) atomicAdd(&g_cnt[dst[e]], 1);
}

// ---------------- w = W2 @ Wl  (64 threads), b2wl ----------------
__global__ void w64_k(const float* __restrict__ W2,
                      const float* __restrict__ b2,
                      const float* __restrict__ Wl) {
    int i = threadIdx.x;
    if (i < NH) {
        float s = 0.f;
#pragma unroll
        for (int j = 0; j < NH; j++) s = fmaf(W2[i * NH + j], Wl[j], s);
        g_w64[i] = s;
    }
    if (i == 0) {
        float s = 0.f;
        for (int j = 0; j < NH; j++) s = fmaf(b2[j], Wl[j], s);
        g_b2wl = s;
    }
}

// ---------------- stage 1: per-tile sums + dinv (fused) ----------------
__global__ void tsum_k() {
    __shared__ int sm[TILE];
    int t = threadIdx.x;
    int i = blockIdx.x * TILE + t;
    int c = (i < NN) ? g_cnt[i] : 0;
    if (i < NN) g_dinv[i] = rsqrtf((float)(c + 1));  // +1 self loop
    sm[t] = c;
    __syncthreads();
#pragma unroll
    for (int off = TILE / 2; off > 0; off >>= 1) {
        if (t < off) sm[t] += sm[t + off];
        __syncthreads();
    }
    if (t == 0) g_tsum[blockIdx.x] = sm[0];
}

// ---------------- stage 2: scan tile sums ----------------
__global__ void toff_k() {
    __shared__ int sm[256];
    int t = threadIdx.x;
    int v = (t < NT) ? g_tsum[t] : 0;
    sm[t] = v;
    __syncthreads();
#pragma unroll
    for (int off = 1; off < 256; off <<= 1) {
        int u = (t >= off) ? sm[t - off] : 0;
        __syncthreads();
        sm[t] += u;
        __syncthreads();
    }
    if (t < NT) g_toff[t] = sm[t] - v;
    if (t == 255) g_rowptr[NN] = sm[255];
}

// ---------------- stage 3: per-tile exclusive scan -> rowptr & cursor ----------------
__global__ void tscan_k() {
    __shared__ int sm[TILE];
    int t = threadIdx.x;
    int i = blockIdx.x * TILE + t;
    int v = (i < NN) ? g_cnt[i] : 0;
    sm[t] = v;
    __syncthreads();
#pragma unroll
    for (int off = 1; off < TILE; off <<= 1) {
        int u = (t >= off) ? sm[t - off] : 0;
        __syncthreads();
        sm[t] += u;
        __syncthreads();
    }
    if (i < NN) {
        int pos = g_toff[blockIdx.x] + sm[t] - v;
        g_rowptr[i] = pos;
        g_cursor[i] = pos;
    }
}

// ---------------- scatter edges into CSR (packed int2) ----------------
__global__ void scatter_k(const int* __restrict__ src,
                          const int* __restrict__ dst) {
    int e = blockIdx.x * blockDim.x + threadIdx.x;
    if (e < NE) {
        int s = src[e];
        int d = dst[e];
        int pos = atomicAdd(&g_cursor[d], 1);
        g_csr[pos] = make_int2(s, __float_as_int(g_dinv[s] * g_dinv[d]));
    }
}

// ---------------- fp32 SGEMM: g_h[M x 64] = A[M x 128] @ W1[128 x 64] ----------------
// 128x64 tile, BK=16, 256 threads, 8x4 microtile.
__global__ void gemm1_k(const float* __restrict__ A,
                        const float* __restrict__ W, int M) {
    float* __restrict__ C = g_h;
    __shared__ float As[16][132];  // [k][m], padded
    __shared__ float Bs[16][64];   // [k][n]

    int tid = threadIdx.x;
    int tx = tid & 15;             // 16 col-groups * 4 = 64
    int ty = tid >> 4;             // 16 row-groups * 8 = 128
    int rowBase = blockIdx.x * 128;

    float acc[8][4];
#pragma unroll
    for (int i = 0; i < 8; i++)
#pragma unroll
        for (int j = 0; j < 4; j++) acc[i][j] = 0.f;

    for (int k0 = 0; k0 < NF; k0 += 16) {
        {   // A tile: 128 rows x 16 k -> 512 float4, 2 per thread
            int r  = tid >> 1;           // 0..127
            int kq = (tid & 1) * 8;      // 0 or 8
            int row = rowBase + r;
            float4 a0 = make_float4(0, 0, 0, 0), a1 = a0;
            if (row < M) {
                const float* p = &A[(size_t)row * NF + k0 + kq];
                a0 = *(const float4*)p;
                a1 = *(const float4*)(p + 4);
            }
            As[kq + 0][r] = a0.x; As[kq + 1][r] = a0.y;
            As[kq + 2][r] = a0.z; As[kq + 3][r] = a0.w;
            As[kq + 4][r] = a1.x; As[kq + 5][r] = a1.y;
            As[kq + 6][r] = a1.z; As[kq + 7][r] = a1.w;
        }
        {   // W tile (16 k x 64 n)
            int kr = tid >> 4;
            int nq = (tid & 15) * 4;
            *(float4*)&Bs[kr][nq] = *(const float4*)&W[(size_t)(k0 + kr) * 64 + nq];
        }
        __syncthreads();
#pragma unroll
        for (int k = 0; k < 16; k++) {
            float4 a0 = *(float4*)&As[k][ty * 8];
            float4 a1 = *(float4*)&As[k][ty * 8 + 4];
            float4 b  = *(float4*)&Bs[k][tx * 4];
            float av[8] = {a0.x, a0.y, a0.z, a0.w, a1.x, a1.y, a1.z, a1.w};
#pragma unroll
            for (int i = 0; i < 8; i++) {
                acc[i][0] = fmaf(av[i], b.x, acc[i][0]);
                acc[i][1] = fmaf(av[i], b.y, acc[i][1]);
                acc[i][2] = fmaf(av[i], b.z, acc[i][2]);
                acc[i][3] = fmaf(av[i], b.w, acc[i][3]);
            }
        }
        __syncthreads();
    }
    int r0 = rowBase + ty * 8;
#pragma unroll
    for (int i = 0; i < 8; i++) {
        if (r0 + i < M)
            *(float4*)&C[(size_t)(r0 + i) * 64 + tx * 4] =
                make_float4(acc[i][0], acc[i][1], acc[i][2], acc[i][3]);
    }
}

// ---------------- gather1: warp per node ----------------
// acc = agg(g_h) + dinv^2 * h[node] + b1 ; relu ; z[node] = acc . w64
__global__ void gather1_k(const float* __restrict__ bias) {
    int node = (blockIdx.x * blockDim.x + threadIdx.x) >> 5;
    if (node >= NN) return;
    int lane = threadIdx.x & 31;

    int beg = g_rowptr[node];
    int end = g_rowptr[node + 1];
    const float2* __restrict__ h2 = (const float2*)g_h;

    float2 acc = make_float2(0.f, 0.f);
    for (int j = beg; j < end; j++) {
        int2 e = __ldg(&g_csr[j]);
        float nrm = __int_as_float(e.y);
        float2 v = __ldg(&h2[(size_t)e.x * 32 + lane]);
        acc.x = fmaf(nrm, v.x, acc.x);
        acc.y = fmaf(nrm, v.y, acc.y);
    }
    float di = g_dinv[node];
    float sn = di * di;
    float2 hv = h2[(size_t)node * 32 + lane];
    acc.x = fmaxf(fmaf(sn, hv.x, acc.x) + bias[2 * lane], 0.f);
    acc.y = fmaxf(fmaf(sn, hv.y, acc.y) + bias[2 * lane + 1], 0.f);

    // z = acc . w64 (warp reduce)
    float v = acc.x * g_w64[2 * lane] + acc.y * g_w64[2 * lane + 1];
#pragma unroll
    for (int o = 16; o; o >>= 1) v += __shfl_xor_sync(0xffffffffu, v, o);
    if (lane == 0) g_z[node] = v;
}

// ---------------- gather2: thread per node, scalar agg + pool ----------------
__global__ void gather2_k(const int* __restrict__ batch) {
    int node = blockIdx.x * blockDim.x + threadIdx.x;
    if (node >= NN) return;
    int beg = g_rowptr[node];
    int end = g_rowptr[node + 1];
    float s = 0.f;
    for (int j = beg; j < end; j++) {
        int2 e = __ldg(&g_csr[j]);
        s = fmaf(__int_as_float(e.y), __ldg(&g_z[e.x]), s);
    }
    float di = g_dinv[node];
    s = fmaf(di * di, g_z[node], s);
    int g = batch[node];
    atomicAdd(&g_pool_s[g], s);
    atomicAdd(&g_gcnt[g], 1);
}

// ---------------- final ----------------
__global__ void final_k(const float* __restrict__ bl, float* __restrict__ out) {
    int g = blockIdx.x * blockDim.x + threadIdx.x;
    if (g >= NG) return;
    float c = (float)g_gcnt[g];
    out[g] = g_pool_s[g] / fmaxf(c, 1.f) + g_b2wl + bl[0];
}

// ---------------- launch ----------------
extern "C" void kernel_launch(void* const* d_in, const int* in_sizes, int n_in,
                              void* d_out, int out_size) {
    const float* x     = (const float*)d_in[0];
    const int*   ei    = (const int*)d_in[1];    // int32 (JAX x64 disabled)
    const int*   batch = (const int*)d_in[2];
    const float* W1    = (const float*)d_in[3];
    const float* b1    = (const float*)d_in[4];
    const float* W2    = (const float*)d_in[5];
    const float* b2    = (const float*)d_in[6];
    const float* Wl    = (const float*)d_in[7];
    const float* bl    = (const float*)d_in[8];
    float* out = (float*)d_out;

    const int* src = ei;
    const int* dst = ei + NE;

    init_k   <<<(NN + 255) / 256, 256>>>();
    count_k  <<<(NE + 255) / 256, 256>>>(dst);
    w64_k    <<<1, 64>>>(W2, b2, Wl);
    tsum_k   <<<NT, TILE>>>();
    toff_k   <<<1, 256>>>();
    tscan_k  <<<NT, TILE>>>();
    scatter_k<<<(NE + 255) / 256, 256>>>(src, dst);

    gemm1_k  <<<(NN + 127) / 128, 256>>>(x, W1, NN);
    gather1_k<<<(NN * 32 + 255) / 256, 256>>>(b1);
    gather2_k<<<(NN + 255) / 256, 256>>>(batch);
    final_k  <<<1, NG>>>(bl, out);
}